// round 15
// baseline (speedup 1.0000x reference)
#include <cuda_runtime.h>
#include <cuda_bf16.h>

#define NDOF 7
#define GRAV 9.81f
#define TPB 128
#define NV4 (TPB*NDOF/4)   // 224 float4 per array per block

// Packed per-joint params: float4 so constant accesses are wide/uniform loads.
// Rf rows: rot_fix[d+1] row-major (w pad). u = Rfix^T p. mc.w = mass.
// Io0.w = damping.
struct JP4 {
    float4 Rf0, Rf1, Rf2;
    float4 u, mc;
    float4 Io0, Io1, Io2;
};

__device__ JP4 g_stage4[NDOF];
__constant__ JP4 c_par4[NDOF];

__global__ void prep_kernel(const float* __restrict__ rot_fix,
                            const float* __restrict__ trans_fix,
                            const float* __restrict__ mass,
                            const float* __restrict__ com,
                            const float* __restrict__ inertia,
                            const float* __restrict__ damping) {
    int d = threadIdx.x;
    if (d >= NDOF) return;
    float R[9];
#pragma unroll
    for (int k = 0; k < 9; k++) R[k] = rot_fix[(d+1)*9 + k];
    float p0 = trans_fix[(d+1)*3+0], p1 = trans_fix[(d+1)*3+1], p2 = trans_fix[(d+1)*3+2];
    float u0 = R[0]*p0 + R[3]*p1 + R[6]*p2;
    float u1 = R[1]*p0 + R[4]*p1 + R[7]*p2;
    float u2 = R[2]*p0 + R[5]*p1 + R[8]*p2;
    float m = mass[d+1];
    float c0 = com[(d+1)*3+0], c1 = com[(d+1)*3+1], c2 = com[(d+1)*3+2];
    float cc = c0*c0 + c1*c1 + c2*c2;
    float cv[3] = {c0, c1, c2};
    float Io[9];
#pragma unroll
    for (int i = 0; i < 3; i++)
#pragma unroll
        for (int j = 0; j < 3; j++)
            Io[i*3+j] = inertia[(d+1)*9 + i*3 + j] + m * ((i == j ? cc : 0.f) - cv[i]*cv[j]);

    JP4 P;
    P.Rf0 = make_float4(R[0], R[1], R[2], 0.f);
    P.Rf1 = make_float4(R[3], R[4], R[5], 0.f);
    P.Rf2 = make_float4(R[6], R[7], R[8], 0.f);
    P.u   = make_float4(u0, u1, u2, 0.f);
    P.mc  = make_float4(m*c0, m*c1, m*c2, m);
    P.Io0 = make_float4(Io[0], Io[1], Io[2], damping[d]);
    P.Io1 = make_float4(Io[3], Io[4], Io[5], 0.f);
    P.Io2 = make_float4(Io[6], Io[7], Io[8], 0.f);
    g_stage4[d] = P;
}

// o = M^T v with M given as rows r0,r1,r2
__device__ __forceinline__ void mtv4(const float4& r0, const float4& r1, const float4& r2,
                                     const float v[3], float o[3]) {
    o[0] = r0.x*v[0] + r1.x*v[1] + r2.x*v[2];
    o[1] = r0.y*v[0] + r1.y*v[1] + r2.y*v[2];
    o[2] = r0.z*v[0] + r1.z*v[1] + r2.z*v[2];
}
// o = M v with rows
__device__ __forceinline__ void mv4(const float4& r0, const float4& r1, const float4& r2,
                                    const float v[3], float o[3]) {
    o[0] = r0.x*v[0] + r0.y*v[1] + r0.z*v[2];
    o[1] = r1.x*v[0] + r1.y*v[1] + r1.z*v[2];
    o[2] = r2.x*v[0] + r2.y*v[1] + r2.z*v[2];
}
__device__ __forceinline__ void cross3(const float a[3], const float b[3], float o[3]) {
    o[0] = a[1]*b[2] - a[2]*b[1];
    o[1] = a[2]*b[0] - a[0]*b[2];
    o[2] = a[0]*b[1] - a[1]*b[0];
}
// Rot_K(angle)^T v (K: 2=z, 1=y); s includes the axis sign.
template<int K>
__device__ __forceinline__ void rotT(float s, float c, const float v[3], float o[3]) {
    if (K == 2) { o[0] = c*v[0] + s*v[1]; o[1] = c*v[1] - s*v[0]; o[2] = v[2]; }
    else        { o[0] = c*v[0] - s*v[2]; o[1] = v[1];            o[2] = c*v[2] + s*v[0]; }
}
// Rot_K(angle) v
template<int K>
__device__ __forceinline__ void rotF(float s, float c, const float v[3], float o[3]) {
    if (K == 2) { o[0] = c*v[0] - s*v[1]; o[1] = s*v[0] + c*v[1]; o[2] = v[2]; }
    else        { o[0] = c*v[0] + s*v[2]; o[1] = v[1];            o[2] = c*v[2] - s*v[0]; }
}

// smem wrench buffer layout: slots [d*8 + k][TPB], k: 0-2 fl, 3-5 fa, 6 s, 7 c
#define WSLOT(d,k) (((d)*8+(k))*TPB)

template<int K, bool NEG>
__device__ __forceinline__ void fwd_step(
    const JP4& Pc, float qv, float qdv, float qddv,
    float vl[3], float va[3], float al[3], float aa[3],
    float* __restrict__ wr)
{
    const float4 Rf0 = Pc.Rf0, Rf1 = Pc.Rf1, Rf2 = Pc.Rf2;
    const float4 U   = Pc.u;
    const float4 MC  = Pc.mc;            // .w = m
    const float4 Io0 = Pc.Io0, Io1 = Pc.Io1, Io2 = Pc.Io2;
    const float  m   = MC.w;
    const float  mc[3] = {MC.x, MC.y, MC.z};
    const float  u[3] = {U.x, U.y, U.z};

    float si, ci;
    __sincosf(qv, &si, &ci);
    float s  = NEG ? -si   : si;
    float w  = NEG ? -qdv  : qdv;
    float wd = NEG ? -qddv : qddv;

    // rotate state through Rfix^T, fold the u-cross BEFORE the joint rotation:
    //   vl' = Rot^T( Rfix^T vl - u x (Rfix^T va) )   [cross preserved by rotation]
    float hva[3], hvl[3], haa[3], hal[3];
    mtv4(Rf0, Rf1, Rf2, va, hva);
    mtv4(Rf0, Rf1, Rf2, vl, hvl);
    mtv4(Rf0, Rf1, Rf2, aa, haa);
    mtv4(Rf0, Rf1, Rf2, al, hal);

    float tvl[3], tal[3];
    tvl[0] = hvl[0] - u[1]*hva[2] + u[2]*hva[1];
    tvl[1] = hvl[1] - u[2]*hva[0] + u[0]*hva[2];
    tvl[2] = hvl[2] - u[0]*hva[1] + u[1]*hva[0];
    tal[0] = hal[0] - u[1]*haa[2] + u[2]*haa[1];
    tal[1] = hal[1] - u[2]*haa[0] + u[0]*haa[2];
    tal[2] = hal[2] - u[0]*haa[1] + u[1]*haa[0];

    rotT<K>(s, ci, tvl, vl);
    rotT<K>(s, ci, hva, va);
    if (K == 2) va[2] += w; else va[1] += w;

    rotT<K>(s, ci, tal, al);
    rotT<K>(s, ci, haa, aa);
    if (K == 2) {
        aa[2] += wd;
        aa[0] += w*va[1]; aa[1] -= w*va[0];
        al[0] += w*vl[1]; al[1] -= w*vl[0];
    } else {
        aa[1] += wd;
        aa[0] -= w*va[2]; aa[2] += w*va[0];
        al[0] -= w*vl[2]; al[2] += w*vl[0];
    }

    // inertial wrench
    float Ial[3], Iaa[3], Ivl[3], Iva[3], tv[3], cx[3];
    cross3(aa, mc, cx);
    Ial[0] = m*al[0] + cx[0]; Ial[1] = m*al[1] + cx[1]; Ial[2] = m*al[2] + cx[2];
    mv4(Io0, Io1, Io2, aa, tv);
    cross3(mc, al, cx);
    Iaa[0] = tv[0] + cx[0]; Iaa[1] = tv[1] + cx[1]; Iaa[2] = tv[2] + cx[2];

    cross3(va, mc, cx);
    Ivl[0] = m*vl[0] + cx[0]; Ivl[1] = m*vl[1] + cx[1]; Ivl[2] = m*vl[2] + cx[2];
    mv4(Io0, Io1, Io2, va, tv);
    cross3(mc, vl, cx);
    Iva[0] = tv[0] + cx[0]; Iva[1] = tv[1] + cx[1]; Iva[2] = tv[2] + cx[2];

    cross3(va, Ivl, cx);
    wr[0]     = Ial[0] + cx[0];
    wr[1*TPB] = Ial[1] + cx[1];
    wr[2*TPB] = Ial[2] + cx[2];
    float cx2[3];
    cross3(va, Iva, cx);
    cross3(vl, Ivl, cx2);
    wr[3*TPB] = Iaa[0] + cx[0] + cx2[0];
    wr[4*TPB] = Iaa[1] + cx[1] + cx2[1];
    wr[5*TPB] = Iaa[2] + cx[2] + cx2[2];
    wr[6*TPB] = s;
    wr[7*TPB] = ci;
}

template<int K, bool NEG>
__device__ __forceinline__ float bwd_step(
    const JP4& Pc, float qdv,
    const float* __restrict__ wr,   // already offset by WSLOT(d,0)+t
    float cl[3], float ca[3])
{
    const float4 Rf0 = Pc.Rf0, Rf1 = Pc.Rf1, Rf2 = Pc.Rf2;
    const float4 U   = Pc.u;
    const float4 Io0 = Pc.Io0;      // .w = damping
    const float  u[3] = {U.x, U.y, U.z};

    float s  = wr[6*TPB];
    float ci = wr[7*TPB];

    float tl[3] = {wr[0]     + cl[0], wr[1*TPB] + cl[1], wr[2*TPB] + cl[2]};
    float ta[3] = {wr[3*TPB] + ca[0], wr[4*TPB] + ca[1], wr[5*TPB] + ca[2]};

    float axc = (K == 2) ? ta[2] : ta[1];
    float tau = (NEG ? -axc : axc) + Io0.w * qdv;

    // nl = Rfix (Rot tl)
    // na = Rfix (Rot ta) + p x nl = Rfix( Rot ta + u x (Rot tl) )
    float wtl[3], wta[3], g[3];
    rotF<K>(s, ci, tl, wtl);
    rotF<K>(s, ci, ta, wta);
    g[0] = wta[0] + u[1]*wtl[2] - u[2]*wtl[1];
    g[1] = wta[1] + u[2]*wtl[0] - u[0]*wtl[2];
    g[2] = wta[2] + u[0]*wtl[1] - u[1]*wtl[0];
    mv4(Rf0, Rf1, Rf2, wtl, cl);
    mv4(Rf0, Rf1, Rf2, g, ca);
    return tau;
}

// NOTE: assumes B % TPB == 0 (dataset: B = 524288 = 4096 * 128). int32 indexing
// throughout (B*NDOF = 3.67M << 2^31).
__global__ void __launch_bounds__(TPB, 5)
rnea_kernel(const float4* __restrict__ q4,
            const float4* __restrict__ qd4,
            const float4* __restrict__ qdd4,
            float4* __restrict__ out4) {
    __shared__ __align__(16) float sq[TPB*NDOF];
    __shared__ __align__(16) float sqd[TPB*NDOF];
    __shared__ __align__(16) float sqdd[TPB*NDOF];
    __shared__ float wr[8*NDOF*TPB];   // per-link: fl(3), fa(3), s, c
    const int t = threadIdx.x;
    const int b4 = blockIdx.x * NV4;   // float4 base of this block's chunk

    // ---- coalesced vectorized input staging (224 float4 per array) ----
    {
        float4* s1 = (float4*)sq;
        float4* s2 = (float4*)sqd;
        float4* s3 = (float4*)sqdd;
        s1[t] = q4[b4 + t];
        s2[t] = qd4[b4 + t];
        s3[t] = qdd4[b4 + t];
        int t2 = TPB + t;
        if (t2 < NV4) {
            s1[t2] = q4[b4 + t2];
            s2[t2] = qd4[b4 + t2];
            s3[t2] = qdd4[b4 + t2];
        }
    }
    __syncthreads();

    float vl[3] = {0.f, 0.f, 0.f};
    float va[3] = {0.f, 0.f, 0.f};
    float al[3] = {0.f, 0.f, GRAV};
    float aa[3] = {0.f, 0.f, 0.f};

    const float* Q  = sq  + t*NDOF;
    const float* QD = sqd + t*NDOF;
    const float* QA = sqdd + t*NDOF;

    // joint axes: [z, y, z, -y, z, y, z]
    fwd_step<2,false>(c_par4[0], Q[0], QD[0], QA[0], vl, va, al, aa, wr + WSLOT(0,0) + t);
    fwd_step<1,false>(c_par4[1], Q[1], QD[1], QA[1], vl, va, al, aa, wr + WSLOT(1,0) + t);
    fwd_step<2,false>(c_par4[2], Q[2], QD[2], QA[2], vl, va, al, aa, wr + WSLOT(2,0) + t);
    fwd_step<1,true >(c_par4[3], Q[3], QD[3], QA[3], vl, va, al, aa, wr + WSLOT(3,0) + t);
    fwd_step<2,false>(c_par4[4], Q[4], QD[4], QA[4], vl, va, al, aa, wr + WSLOT(4,0) + t);
    fwd_step<1,false>(c_par4[5], Q[5], QD[5], QA[5], vl, va, al, aa, wr + WSLOT(5,0) + t);
    fwd_step<2,false>(c_par4[6], Q[6], QD[6], QA[6], vl, va, al, aa, wr + WSLOT(6,0) + t);

    float cl[3] = {0.f, 0.f, 0.f};
    float ca[3] = {0.f, 0.f, 0.f};
    float tau6 = bwd_step<2,false>(c_par4[6], QD[6], wr + WSLOT(6,0) + t, cl, ca);
    float tau5 = bwd_step<1,false>(c_par4[5], QD[5], wr + WSLOT(5,0) + t, cl, ca);
    float tau4 = bwd_step<2,false>(c_par4[4], QD[4], wr + WSLOT(4,0) + t, cl, ca);
    float tau3 = bwd_step<1,true >(c_par4[3], QD[3], wr + WSLOT(3,0) + t, cl, ca);
    float tau2 = bwd_step<2,false>(c_par4[2], QD[2], wr + WSLOT(2,0) + t, cl, ca);
    float tau1 = bwd_step<1,false>(c_par4[1], QD[1], wr + WSLOT(1,0) + t, cl, ca);
    float tau0 = bwd_step<2,false>(c_par4[0], QD[0], wr + WSLOT(0,0) + t, cl, ca);

    __syncthreads();   // all wr reads done; safe to overwrite sqdd
    float* TAU = sqdd + t*NDOF;
    TAU[0] = tau0; TAU[1] = tau1; TAU[2] = tau2; TAU[3] = tau3;
    TAU[4] = tau4; TAU[5] = tau5; TAU[6] = tau6;

    __syncthreads();
    // vectorized coalesced output store
    {
        const float4* s3 = (const float4*)sqdd;
        out4[b4 + t] = s3[t];
        int t2 = TPB + t;
        if (t2 < NV4) out4[b4 + t2] = s3[t2];
    }
}

extern "C" void kernel_launch(void* const* d_in, const int* in_sizes, int n_in,
                              void* d_out, int out_size) {
    const float* q          = (const float*)d_in[0];
    const float* qd         = (const float*)d_in[1];
    const float* qdd_des    = (const float*)d_in[2];
    const float* rot_fix    = (const float*)d_in[3];
    const float* trans_fix  = (const float*)d_in[4];
    const float* mass       = (const float*)d_in[6];
    const float* com        = (const float*)d_in[7];
    const float* inertia    = (const float*)d_in[8];
    const float* damping    = (const float*)d_in[9];

    int B = in_sizes[0] / NDOF;

    prep_kernel<<<1, 32>>>(rot_fix, trans_fix, mass, com, inertia, damping);

    void* src = nullptr;
    cudaGetSymbolAddress(&src, g_stage4);
    cudaMemcpyToSymbolAsync(c_par4, src, sizeof(JP4) * NDOF, 0,
                            cudaMemcpyDeviceToDevice, 0);

    int blocks = B / TPB;   // B = 524288 -> 4096 exact
    rnea_kernel<<<blocks, TPB>>>((const float4*)q, (const float4*)qd,
                                 (const float4*)qdd_des, (float4*)d_out);
}

// round 17
// speedup vs baseline: 1.0559x; 1.0559x over previous
#include <cuda_runtime.h>
#include <cuda_bf16.h>

#define NDOF 7
#define GRAV 9.81f
#define TPB 128
#define NV4 (TPB*NDOF/4)   // 224 float4 per array per block

// Packed per-joint params: float4 so constant accesses are wide/uniform loads.
// Rf rows: rot_fix[d+1] row-major (w pad). u = Rfix^T p. mc.w = mass.
// Io0.w = damping.
struct JP4 {
    float4 Rf0, Rf1, Rf2;
    float4 u, mc;
    float4 Io0, Io1, Io2;
};

__device__ JP4 g_stage4[NDOF];
__constant__ JP4 c_par4[NDOF];

__global__ void prep_kernel(const float* __restrict__ rot_fix,
                            const float* __restrict__ trans_fix,
                            const float* __restrict__ mass,
                            const float* __restrict__ com,
                            const float* __restrict__ inertia,
                            const float* __restrict__ damping) {
    int d = threadIdx.x;
    if (d >= NDOF) return;
    float R[9];
#pragma unroll
    for (int k = 0; k < 9; k++) R[k] = rot_fix[(d+1)*9 + k];
    float p0 = trans_fix[(d+1)*3+0], p1 = trans_fix[(d+1)*3+1], p2 = trans_fix[(d+1)*3+2];
    float u0 = R[0]*p0 + R[3]*p1 + R[6]*p2;
    float u1 = R[1]*p0 + R[4]*p1 + R[7]*p2;
    float u2 = R[2]*p0 + R[5]*p1 + R[8]*p2;
    float m = mass[d+1];
    float c0 = com[(d+1)*3+0], c1 = com[(d+1)*3+1], c2 = com[(d+1)*3+2];
    float cc = c0*c0 + c1*c1 + c2*c2;
    float cv[3] = {c0, c1, c2};
    float Io[9];
#pragma unroll
    for (int i = 0; i < 3; i++)
#pragma unroll
        for (int j = 0; j < 3; j++)
            Io[i*3+j] = inertia[(d+1)*9 + i*3 + j] + m * ((i == j ? cc : 0.f) - cv[i]*cv[j]);

    JP4 P;
    P.Rf0 = make_float4(R[0], R[1], R[2], 0.f);
    P.Rf1 = make_float4(R[3], R[4], R[5], 0.f);
    P.Rf2 = make_float4(R[6], R[7], R[8], 0.f);
    P.u   = make_float4(u0, u1, u2, 0.f);
    P.mc  = make_float4(m*c0, m*c1, m*c2, m);
    P.Io0 = make_float4(Io[0], Io[1], Io[2], damping[d]);
    P.Io1 = make_float4(Io[3], Io[4], Io[5], 0.f);
    P.Io2 = make_float4(Io[6], Io[7], Io[8], 0.f);
    g_stage4[d] = P;
}

// o = M^T v with M given as rows r0,r1,r2
__device__ __forceinline__ void mtv4(const float4& r0, const float4& r1, const float4& r2,
                                     const float v[3], float o[3]) {
    o[0] = r0.x*v[0] + r1.x*v[1] + r2.x*v[2];
    o[1] = r0.y*v[0] + r1.y*v[1] + r2.y*v[2];
    o[2] = r0.z*v[0] + r1.z*v[1] + r2.z*v[2];
}
// o = M v with rows
__device__ __forceinline__ void mv4(const float4& r0, const float4& r1, const float4& r2,
                                    const float v[3], float o[3]) {
    o[0] = r0.x*v[0] + r0.y*v[1] + r0.z*v[2];
    o[1] = r1.x*v[0] + r1.y*v[1] + r1.z*v[2];
    o[2] = r2.x*v[0] + r2.y*v[1] + r2.z*v[2];
}
__device__ __forceinline__ void cross3(const float a[3], const float b[3], float o[3]) {
    o[0] = a[1]*b[2] - a[2]*b[1];
    o[1] = a[2]*b[0] - a[0]*b[2];
    o[2] = a[0]*b[1] - a[1]*b[0];
}
// Rot_K(angle)^T v (K: 2=z, 1=y); s includes the axis sign.
template<int K>
__device__ __forceinline__ void rotT(float s, float c, const float v[3], float o[3]) {
    if (K == 2) { o[0] = c*v[0] + s*v[1]; o[1] = c*v[1] - s*v[0]; o[2] = v[2]; }
    else        { o[0] = c*v[0] - s*v[2]; o[1] = v[1];            o[2] = c*v[2] + s*v[0]; }
}
// Rot_K(angle) v
template<int K>
__device__ __forceinline__ void rotF(float s, float c, const float v[3], float o[3]) {
    if (K == 2) { o[0] = c*v[0] - s*v[1]; o[1] = s*v[0] + c*v[1]; o[2] = v[2]; }
    else        { o[0] = c*v[0] + s*v[2]; o[1] = v[1];            o[2] = c*v[2] - s*v[0]; }
}

// smem wrench buffer layout: slots [d*6 + k][TPB], k: 0-2 fl, 3-5 fa
#define WSLOT(d,k) (((d)*6+(k))*TPB)

template<int K, bool NEG>
__device__ __forceinline__ void fwd_step(
    const JP4& Pc, float qv, float qdv, float qddv,
    float vl[3], float va[3], float al[3], float aa[3],
    float* __restrict__ wr, float& sOut, float& cOut)
{
    const float4 Rf0 = Pc.Rf0, Rf1 = Pc.Rf1, Rf2 = Pc.Rf2;
    const float4 U   = Pc.u;
    const float4 MC  = Pc.mc;            // .w = m
    const float4 Io0 = Pc.Io0, Io1 = Pc.Io1, Io2 = Pc.Io2;
    const float  m   = MC.w;
    const float  mc[3] = {MC.x, MC.y, MC.z};
    const float  u[3] = {U.x, U.y, U.z};

    float si, ci;
    __sincosf(qv, &si, &ci);
    float s  = NEG ? -si   : si;
    float w  = NEG ? -qdv  : qdv;
    float wd = NEG ? -qddv : qddv;
    sOut = s; cOut = ci;

    // rotate state through Rfix^T, fold the u-cross BEFORE the joint rotation:
    //   vl' = Rot^T( Rfix^T vl - u x (Rfix^T va) )   [cross preserved by rotation]
    float hva[3], hvl[3], haa[3], hal[3];
    mtv4(Rf0, Rf1, Rf2, va, hva);
    mtv4(Rf0, Rf1, Rf2, vl, hvl);
    mtv4(Rf0, Rf1, Rf2, aa, haa);
    mtv4(Rf0, Rf1, Rf2, al, hal);

    float tvl[3], tal[3];
    tvl[0] = hvl[0] - u[1]*hva[2] + u[2]*hva[1];
    tvl[1] = hvl[1] - u[2]*hva[0] + u[0]*hva[2];
    tvl[2] = hvl[2] - u[0]*hva[1] + u[1]*hva[0];
    tal[0] = hal[0] - u[1]*haa[2] + u[2]*haa[1];
    tal[1] = hal[1] - u[2]*haa[0] + u[0]*haa[2];
    tal[2] = hal[2] - u[0]*haa[1] + u[1]*haa[0];

    rotT<K>(s, ci, tvl, vl);
    rotT<K>(s, ci, hva, va);
    if (K == 2) va[2] += w; else va[1] += w;

    rotT<K>(s, ci, tal, al);
    rotT<K>(s, ci, haa, aa);
    if (K == 2) {
        aa[2] += wd;
        aa[0] += w*va[1]; aa[1] -= w*va[0];
        al[0] += w*vl[1]; al[1] -= w*vl[0];
    } else {
        aa[1] += wd;
        aa[0] -= w*va[2]; aa[2] += w*va[0];
        al[0] -= w*vl[2]; al[2] += w*vl[0];
    }

    // inertial wrench
    float Ial[3], Iaa[3], Ivl[3], Iva[3], tv[3], cx[3];
    cross3(aa, mc, cx);
    Ial[0] = m*al[0] + cx[0]; Ial[1] = m*al[1] + cx[1]; Ial[2] = m*al[2] + cx[2];
    mv4(Io0, Io1, Io2, aa, tv);
    cross3(mc, al, cx);
    Iaa[0] = tv[0] + cx[0]; Iaa[1] = tv[1] + cx[1]; Iaa[2] = tv[2] + cx[2];

    cross3(va, mc, cx);
    Ivl[0] = m*vl[0] + cx[0]; Ivl[1] = m*vl[1] + cx[1]; Ivl[2] = m*vl[2] + cx[2];
    mv4(Io0, Io1, Io2, va, tv);
    cross3(mc, vl, cx);
    Iva[0] = tv[0] + cx[0]; Iva[1] = tv[1] + cx[1]; Iva[2] = tv[2] + cx[2];

    cross3(va, Ivl, cx);
    wr[0]     = Ial[0] + cx[0];
    wr[1*TPB] = Ial[1] + cx[1];
    wr[2*TPB] = Ial[2] + cx[2];
    float cx2[3];
    cross3(va, Iva, cx);
    cross3(vl, Ivl, cx2);
    wr[3*TPB] = Iaa[0] + cx[0] + cx2[0];
    wr[4*TPB] = Iaa[1] + cx[1] + cx2[1];
    wr[5*TPB] = Iaa[2] + cx[2] + cx2[2];
}

template<int K, bool NEG>
__device__ __forceinline__ float bwd_step(
    const JP4& Pc, float qdv, float s, float ci,
    const float* __restrict__ wr,   // already offset by WSLOT(d,0)+t
    float cl[3], float ca[3])
{
    const float4 Rf0 = Pc.Rf0, Rf1 = Pc.Rf1, Rf2 = Pc.Rf2;
    const float4 U   = Pc.u;
    const float4 Io0 = Pc.Io0;      // .w = damping
    const float  u[3] = {U.x, U.y, U.z};

    float tl[3] = {wr[0]     + cl[0], wr[1*TPB] + cl[1], wr[2*TPB] + cl[2]};
    float ta[3] = {wr[3*TPB] + ca[0], wr[4*TPB] + ca[1], wr[5*TPB] + ca[2]};

    float axc = (K == 2) ? ta[2] : ta[1];
    float tau = (NEG ? -axc : axc) + Io0.w * qdv;

    // nl = Rfix (Rot tl)
    // na = Rfix (Rot ta) + p x nl = Rfix( Rot ta + u x (Rot tl) )
    float wtl[3], wta[3], g[3];
    rotF<K>(s, ci, tl, wtl);
    rotF<K>(s, ci, ta, wta);
    g[0] = wta[0] + u[1]*wtl[2] - u[2]*wtl[1];
    g[1] = wta[1] + u[2]*wtl[0] - u[0]*wtl[2];
    g[2] = wta[2] + u[0]*wtl[1] - u[1]*wtl[0];
    mv4(Rf0, Rf1, Rf2, wtl, cl);
    mv4(Rf0, Rf1, Rf2, g, ca);
    return tau;
}

// NOTE: assumes B % TPB == 0 (dataset: B = 524288 = 4096 * 128). int32 indexing.
__global__ void __launch_bounds__(TPB, 6)
rnea_kernel(const float4* __restrict__ q4,
            const float4* __restrict__ qd4,
            const float4* __restrict__ qdd4,
            float4* __restrict__ out4) {
    __shared__ __align__(16) float sq[TPB*NDOF];
    __shared__ __align__(16) float sqd[TPB*NDOF];
    __shared__ __align__(16) float sqdd[TPB*NDOF];
    __shared__ float wr[6*NDOF*TPB];   // per-link wrench: fl(3), fa(3)
    const int t = threadIdx.x;
    const int b4 = blockIdx.x * NV4;   // float4 base of this block's chunk

    // ---- coalesced vectorized input staging (224 float4 per array) ----
    {
        float4* s1 = (float4*)sq;
        float4* s2 = (float4*)sqd;
        float4* s3 = (float4*)sqdd;
        s1[t] = q4[b4 + t];
        s2[t] = qd4[b4 + t];
        s3[t] = qdd4[b4 + t];
        int t2 = TPB + t;
        if (t2 < NV4) {
            s1[t2] = q4[b4 + t2];
            s2[t2] = qd4[b4 + t2];
            s3[t2] = qdd4[b4 + t2];
        }
    }
    __syncthreads();

    float vl[3] = {0.f, 0.f, 0.f};
    float va[3] = {0.f, 0.f, 0.f};
    float al[3] = {0.f, 0.f, GRAV};
    float aa[3] = {0.f, 0.f, 0.f};

    float* SQ = sq  + t*NDOF;     // q, then reused for s
    float* SC = sqdd + t*NDOF;    // qdd, then reused for c, then tau
    const float* QD = sqd + t*NDOF;

    // joint axes: [z, y, z, -y, z, y, z]
    // fwd_step reads q/qdd from SQ/SC slot d, then overwrites it with s/c.
    {
        float s, c;
        fwd_step<2,false>(c_par4[0], SQ[0], QD[0], SC[0], vl, va, al, aa, wr + WSLOT(0,0) + t, s, c); SQ[0]=s; SC[0]=c;
        fwd_step<1,false>(c_par4[1], SQ[1], QD[1], SC[1], vl, va, al, aa, wr + WSLOT(1,0) + t, s, c); SQ[1]=s; SC[1]=c;
        fwd_step<2,false>(c_par4[2], SQ[2], QD[2], SC[2], vl, va, al, aa, wr + WSLOT(2,0) + t, s, c); SQ[2]=s; SC[2]=c;
        fwd_step<1,true >(c_par4[3], SQ[3], QD[3], SC[3], vl, va, al, aa, wr + WSLOT(3,0) + t, s, c); SQ[3]=s; SC[3]=c;
        fwd_step<2,false>(c_par4[4], SQ[4], QD[4], SC[4], vl, va, al, aa, wr + WSLOT(4,0) + t, s, c); SQ[4]=s; SC[4]=c;
        fwd_step<1,false>(c_par4[5], SQ[5], QD[5], SC[5], vl, va, al, aa, wr + WSLOT(5,0) + t, s, c); SQ[5]=s; SC[5]=c;
        fwd_step<2,false>(c_par4[6], SQ[6], QD[6], SC[6], vl, va, al, aa, wr + WSLOT(6,0) + t, s, c); SQ[6]=s; SC[6]=c;
    }

    float cl[3] = {0.f, 0.f, 0.f};
    float ca[3] = {0.f, 0.f, 0.f};
    // bwd_step reads s from SQ[d], c from SC[d]; tau overwrites SC[d] after use.
    SC[6] = bwd_step<2,false>(c_par4[6], QD[6], SQ[6], SC[6], wr + WSLOT(6,0) + t, cl, ca);
    SC[5] = bwd_step<1,false>(c_par4[5], QD[5], SQ[5], SC[5], wr + WSLOT(5,0) + t, cl, ca);
    SC[4] = bwd_step<2,false>(c_par4[4], QD[4], SQ[4], SC[4], wr + WSLOT(4,0) + t, cl, ca);
    SC[3] = bwd_step<1,true >(c_par4[3], QD[3], SQ[3], SC[3], wr + WSLOT(3,0) + t, cl, ca);
    SC[2] = bwd_step<2,false>(c_par4[2], QD[2], SQ[2], SC[2], wr + WSLOT(2,0) + t, cl, ca);
    SC[1] = bwd_step<1,false>(c_par4[1], QD[1], SQ[1], SC[1], wr + WSLOT(1,0) + t, cl, ca);
    SC[0] = bwd_step<2,false>(c_par4[0], QD[0], SQ[0], SC[0], wr + WSLOT(0,0) + t, cl, ca);

    __syncthreads();
    // vectorized coalesced output store (tau lives in sqdd)
    {
        const float4* s3 = (const float4*)sqdd;
        out4[b4 + t] = s3[t];
        int t2 = TPB + t;
        if (t2 < NV4) out4[b4 + t2] = s3[t2];
    }
}

extern "C" void kernel_launch(void* const* d_in, const int* in_sizes, int n_in,
                              void* d_out, int out_size) {
    const float* q          = (const float*)d_in[0];
    const float* qd         = (const float*)d_in[1];
    const float* qdd_des    = (const float*)d_in[2];
    const float* rot_fix    = (const float*)d_in[3];
    const float* trans_fix  = (const float*)d_in[4];
    const float* mass       = (const float*)d_in[6];
    const float* com        = (const float*)d_in[7];
    const float* inertia    = (const float*)d_in[8];
    const float* damping    = (const float*)d_in[9];

    int B = in_sizes[0] / NDOF;

    prep_kernel<<<1, 32>>>(rot_fix, trans_fix, mass, com, inertia, damping);

    void* src = nullptr;
    cudaGetSymbolAddress(&src, g_stage4);
    cudaMemcpyToSymbolAsync(c_par4, src, sizeof(JP4) * NDOF, 0,
                            cudaMemcpyDeviceToDevice, 0);

    int blocks = B / TPB;   // B = 524288 -> 4096 exact
    rnea_kernel<<<blocks, TPB>>>((const float4*)q, (const float4*)qd,
                                 (const float4*)qdd_des, (float4*)d_out);
}